// round 1
// baseline (speedup 1.0000x reference)
#include <cuda_runtime.h>
#include <math.h>

// Problem constants
#define BATCH 8
#define SEQ   512
#define DMODEL 1024
#define NHEAD 16
#define DK    64
#define TBDIM 64
#define SCALE 0.125f   // 64^-0.5
#define NEGINF -1e30f

#define MROWS (BATCH*SEQ)          // 4096

// Scratch (device globals; no allocation allowed)
__device__ float g_Q[BATCH*NHEAD*SEQ*DK];   // (B,H,S,DK)
__device__ float g_K[BATCH*NHEAD*SEQ*DK];
__device__ float g_V[BATCH*NHEAD*SEQ*DK];
__device__ float g_Tb[BATCH*SEQ*SEQ];       // temporal bias (B,S,S)
__device__ float g_O[MROWS*DMODEL];         // attention output (B,S,D)

// ---------------------------------------------------------------------------
// Kernel 1: temporal bias precompute.
// bias(t) = b2 + sum_j w2[j] * lrelu(t*w1[j] + b1[j]),  t = 1/log(e + mat)
// ---------------------------------------------------------------------------
__global__ void bias_kernel(const float* __restrict__ mat,
                            const float* __restrict__ w1,
                            const float* __restrict__ b1,
                            const float* __restrict__ w2,
                            const float* __restrict__ b2) {
    __shared__ float sw1[TBDIM], sb1[TBDIM], sw2[TBDIM];
    int tid = threadIdx.x;
    if (tid < TBDIM) { sw1[tid] = w1[tid]; sb1[tid] = b1[tid]; sw2[tid] = w2[tid]; }
    __syncthreads();
    int idx = blockIdx.x * blockDim.x + tid;
    if (idx >= BATCH*SEQ*SEQ) return;
    float t = 1.0f / logf(2.718281828459045f + mat[idx]);
    float acc = b2[0];
#pragma unroll
    for (int j = 0; j < TBDIM; j++) {
        float h = fmaf(t, sw1[j], sb1[j]);
        h = (h >= 0.0f) ? h : 0.2f * h;
        acc = fmaf(h, sw2[j], acc);
    }
    g_Tb[idx] = acc;
}

// ---------------------------------------------------------------------------
// Kernel 2: fused QKV GEMM.  C = x @ W + b, scattered to (B,H,S,DK).
// blockIdx.z selects (wq,bq)->g_Q, (wk,bk)->g_K, (wv,bv)->g_V.
// Block tile 64x64, BK=16, 256 threads, 4x4 register micro-tile.
// ---------------------------------------------------------------------------
#define BK 16
__global__ void gemm_qkv(const float* __restrict__ x,
                         const float* __restrict__ wq, const float* __restrict__ bq,
                         const float* __restrict__ wk, const float* __restrict__ bk,
                         const float* __restrict__ wv, const float* __restrict__ bv) {
    int which = blockIdx.z;
    const float* W    = (which == 0) ? wq : (which == 1) ? wk : wv;
    const float* bias = (which == 0) ? bq : (which == 1) ? bk : bv;
    float* out        = (which == 0) ? g_Q : (which == 1) ? g_K : g_V;

    __shared__ float AsT[BK][68];     // transposed A tile (k, m), padded
    __shared__ float Ws[BK][64];      // W tile (k, n)

    int m0 = blockIdx.y * 64;
    int n0 = blockIdx.x * 64;
    int tid = threadIdx.x;
    int tx = tid & 15, ty = tid >> 4;
    int ar = tid >> 2, ac4 = tid & 3;      // A load: 64 rows x 4 float4
    int wr = tid >> 4, wc4 = tid & 15;     // W load: 16 rows x 16 float4

    float acc[4][4] = {};

    for (int k0 = 0; k0 < DMODEL; k0 += BK) {
        float4 av = *(const float4*)&x[(m0 + ar) * DMODEL + k0 + ac4 * 4];
        AsT[ac4*4 + 0][ar] = av.x;
        AsT[ac4*4 + 1][ar] = av.y;
        AsT[ac4*4 + 2][ar] = av.z;
        AsT[ac4*4 + 3][ar] = av.w;
        *(float4*)&Ws[wr][wc4*4] = *(const float4*)&W[(k0 + wr) * DMODEL + n0 + wc4 * 4];
        __syncthreads();
#pragma unroll
        for (int kk = 0; kk < BK; kk++) {
            float4 a4 = *(const float4*)&AsT[kk][ty * 4];
            float4 b4 = *(const float4*)&Ws[kk][tx * 4];
            float a[4] = {a4.x, a4.y, a4.z, a4.w};
            float b[4] = {b4.x, b4.y, b4.z, b4.w};
#pragma unroll
            for (int i = 0; i < 4; i++)
#pragma unroll
                for (int j = 0; j < 4; j++)
                    acc[i][j] = fmaf(a[i], b[j], acc[i][j]);
        }
        __syncthreads();
    }

#pragma unroll
    for (int i = 0; i < 4; i++) {
        int m = m0 + ty * 4 + i;
        int b = m >> 9, s = m & 511;
#pragma unroll
        for (int j = 0; j < 4; j++) {
            int n = n0 + tx * 4 + j;
            int h = n >> 6, d = n & 63;
            out[(((b * NHEAD) + h) * SEQ + s) * DK + d] = acc[i][j] + bias[n];
        }
    }
}

// ---------------------------------------------------------------------------
// Kernel 3: projection GEMM.  d_out = g_O @ w_proj + b_proj  (plain layout)
// ---------------------------------------------------------------------------
__global__ void gemm_proj(const float* __restrict__ W,
                          const float* __restrict__ bias,
                          float* __restrict__ out) {
    __shared__ float AsT[BK][68];
    __shared__ float Ws[BK][64];

    int m0 = blockIdx.y * 64;
    int n0 = blockIdx.x * 64;
    int tid = threadIdx.x;
    int tx = tid & 15, ty = tid >> 4;
    int ar = tid >> 2, ac4 = tid & 3;
    int wr = tid >> 4, wc4 = tid & 15;

    float acc[4][4] = {};

    for (int k0 = 0; k0 < DMODEL; k0 += BK) {
        float4 av = *(const float4*)&g_O[(m0 + ar) * DMODEL + k0 + ac4 * 4];
        AsT[ac4*4 + 0][ar] = av.x;
        AsT[ac4*4 + 1][ar] = av.y;
        AsT[ac4*4 + 2][ar] = av.z;
        AsT[ac4*4 + 3][ar] = av.w;
        *(float4*)&Ws[wr][wc4*4] = *(const float4*)&W[(k0 + wr) * DMODEL + n0 + wc4 * 4];
        __syncthreads();
#pragma unroll
        for (int kk = 0; kk < BK; kk++) {
            float4 a4 = *(const float4*)&AsT[kk][ty * 4];
            float4 b4 = *(const float4*)&Ws[kk][tx * 4];
            float a[4] = {a4.x, a4.y, a4.z, a4.w};
            float b[4] = {b4.x, b4.y, b4.z, b4.w};
#pragma unroll
            for (int i = 0; i < 4; i++)
#pragma unroll
                for (int j = 0; j < 4; j++)
                    acc[i][j] = fmaf(a[i], b[j], acc[i][j]);
        }
        __syncthreads();
    }

#pragma unroll
    for (int i = 0; i < 4; i++) {
        int m = m0 + ty * 4 + i;
#pragma unroll
        for (int j = 0; j < 4; j++) {
            int n = n0 + tx * 4 + j;
            out[m * DMODEL + n] = acc[i][j] + bias[n];
        }
    }
}

// ---------------------------------------------------------------------------
// Kernel 4: causal flash attention with precomputed temporal bias.
// One block per (q-tile 64, head, batch). 256 threads, online softmax.
// Smem: Qs(64x68) KsT(64x68) Vs(64x68) Ss(64x68) + m/l/corr(64 each)
// ---------------------------------------------------------------------------
#define SPAD 68
#define ATTN_SMEM ((4*64*SPAD + 3*64) * 4)

__global__ void attn_kernel(const int* __restrict__ pm) {
    extern __shared__ float sm[];
    float* Qs   = sm;
    float* KsT  = Qs  + 64 * SPAD;
    float* Vs   = KsT + 64 * SPAD;
    float* Ss   = Vs  + 64 * SPAD;
    float* mrow = Ss  + 64 * SPAD;
    float* lrow = mrow + 64;
    float* crow = lrow + 64;

    int qt = blockIdx.x;          // 0..7
    int h  = blockIdx.y;
    int b  = blockIdx.z;
    int tid = threadIdx.x;
    int tx = tid & 15, ty = tid >> 4;

    const float* Qg = g_Q + (size_t)((b * NHEAD + h) * SEQ) * DK;
    const float* Kg = g_K + (size_t)((b * NHEAD + h) * SEQ) * DK;
    const float* Vg = g_V + (size_t)((b * NHEAD + h) * SEQ) * DK;
    const float* Tbb = g_Tb + (size_t)b * SEQ * SEQ;
    int q0 = qt * 64;

    // load Q tile, pre-scaled
    {
        int r = tid >> 4, c4 = tid & 15;
#pragma unroll
        for (int p = 0; p < 4; p++) {
            int rr = r + p * 16;
            float4 v = *(const float4*)&Qg[(q0 + rr) * DK + c4 * 4];
            v.x *= SCALE; v.y *= SCALE; v.z *= SCALE; v.w *= SCALE;
            *(float4*)&Qs[rr * SPAD + c4 * 4] = v;
        }
    }
    if (tid < 64) { mrow[tid] = NEGINF; lrow[tid] = 0.0f; }

    float o[4][4] = {};

    for (int kt = 0; kt <= qt; kt++) {
        // load K (transposed) and V tiles
        {
            int r = tid >> 4, c4 = tid & 15;
#pragma unroll
            for (int p = 0; p < 4; p++) {
                int rr = r + p * 16;
                float4 kv = *(const float4*)&Kg[(kt * 64 + rr) * DK + c4 * 4];
                KsT[(c4*4 + 0) * SPAD + rr] = kv.x;
                KsT[(c4*4 + 1) * SPAD + rr] = kv.y;
                KsT[(c4*4 + 2) * SPAD + rr] = kv.z;
                KsT[(c4*4 + 3) * SPAD + rr] = kv.w;
                *(float4*)&Vs[rr * SPAD + c4 * 4] =
                    *(const float4*)&Vg[(kt * 64 + rr) * DK + c4 * 4];
            }
        }
        __syncthreads();

        // S = Q K^T (scaled)
        float s[4][4] = {};
#pragma unroll
        for (int d = 0; d < 64; d++) {
            float a0 = Qs[(ty*4 + 0) * SPAD + d];
            float a1 = Qs[(ty*4 + 1) * SPAD + d];
            float a2 = Qs[(ty*4 + 2) * SPAD + d];
            float a3 = Qs[(ty*4 + 3) * SPAD + d];
            float4 b4 = *(const float4*)&KsT[d * SPAD + tx * 4];
            s[0][0] = fmaf(a0, b4.x, s[0][0]); s[0][1] = fmaf(a0, b4.y, s[0][1]);
            s[0][2] = fmaf(a0, b4.z, s[0][2]); s[0][3] = fmaf(a0, b4.w, s[0][3]);
            s[1][0] = fmaf(a1, b4.x, s[1][0]); s[1][1] = fmaf(a1, b4.y, s[1][1]);
            s[1][2] = fmaf(a1, b4.z, s[1][2]); s[1][3] = fmaf(a1, b4.w, s[1][3]);
            s[2][0] = fmaf(a2, b4.x, s[2][0]); s[2][1] = fmaf(a2, b4.y, s[2][1]);
            s[2][2] = fmaf(a2, b4.z, s[2][2]); s[2][3] = fmaf(a2, b4.w, s[2][3]);
            s[3][0] = fmaf(a3, b4.x, s[3][0]); s[3][1] = fmaf(a3, b4.y, s[3][1]);
            s[3][2] = fmaf(a3, b4.z, s[3][2]); s[3][3] = fmaf(a3, b4.w, s[3][3]);
        }

        // add temporal bias, apply masks, write to Ss
#pragma unroll
        for (int i = 0; i < 4; i++) {
            int qg = q0 + ty * 4 + i;
            const float* tb = &Tbb[(size_t)qg * SEQ + kt * 64 + tx * 4];
#pragma unroll
            for (int j = 0; j < 4; j++) {
                int kg = kt * 64 + tx * 4 + j;
                float v = s[i][j] + tb[j];
                if (kg > qg || pm[b * SEQ + kg] == 0) v = NEGINF;
                Ss[(ty*4 + i) * SPAD + tx * 4 + j] = v;
            }
        }
        __syncthreads();

        // online softmax update (4 lanes per row)
        {
            int row = tid >> 2, g = tid & 3;
            float* sr = &Ss[row * SPAD + g * 16];
            float mx = NEGINF;
#pragma unroll
            for (int k = 0; k < 16; k++) mx = fmaxf(mx, sr[k]);
            mx = fmaxf(mx, __shfl_xor_sync(0xffffffffu, mx, 1));
            mx = fmaxf(mx, __shfl_xor_sync(0xffffffffu, mx, 2));
            float mold = mrow[row];
            float mnew = fmaxf(mold, mx);
            float corr = __expf(mold - mnew);
            float sum = 0.0f;
#pragma unroll
            for (int k = 0; k < 16; k++) {
                float p = __expf(sr[k] - mnew);
                sr[k] = p;
                sum += p;
            }
            sum += __shfl_xor_sync(0xffffffffu, sum, 1);
            sum += __shfl_xor_sync(0xffffffffu, sum, 2);
            if (g == 0) {
                lrow[row] = lrow[row] * corr + sum;
                mrow[row] = mnew;
                crow[row] = corr;
            }
        }
        __syncthreads();

        // O = O*corr + P V
        float c0 = crow[ty*4 + 0], c1 = crow[ty*4 + 1];
        float c2 = crow[ty*4 + 2], c3 = crow[ty*4 + 3];
#pragma unroll
        for (int j = 0; j < 4; j++) {
            o[0][j] *= c0; o[1][j] *= c1; o[2][j] *= c2; o[3][j] *= c3;
        }
#pragma unroll
        for (int kk = 0; kk < 64; kk++) {
            float a0 = Ss[(ty*4 + 0) * SPAD + kk];
            float a1 = Ss[(ty*4 + 1) * SPAD + kk];
            float a2 = Ss[(ty*4 + 2) * SPAD + kk];
            float a3 = Ss[(ty*4 + 3) * SPAD + kk];
            float4 b4 = *(const float4*)&Vs[kk * SPAD + tx * 4];
            o[0][0] = fmaf(a0, b4.x, o[0][0]); o[0][1] = fmaf(a0, b4.y, o[0][1]);
            o[0][2] = fmaf(a0, b4.z, o[0][2]); o[0][3] = fmaf(a0, b4.w, o[0][3]);
            o[1][0] = fmaf(a1, b4.x, o[1][0]); o[1][1] = fmaf(a1, b4.y, o[1][1]);
            o[1][2] = fmaf(a1, b4.z, o[1][2]); o[1][3] = fmaf(a1, b4.w, o[1][3]);
            o[2][0] = fmaf(a2, b4.x, o[2][0]); o[2][1] = fmaf(a2, b4.y, o[2][1]);
            o[2][2] = fmaf(a2, b4.z, o[2][2]); o[2][3] = fmaf(a2, b4.w, o[2][3]);
            o[3][0] = fmaf(a3, b4.x, o[3][0]); o[3][1] = fmaf(a3, b4.y, o[3][1]);
            o[3][2] = fmaf(a3, b4.z, o[3][2]); o[3][3] = fmaf(a3, b4.w, o[3][3]);
        }
        __syncthreads();
    }

    // normalize and write to g_O (B,S,D) at column h*64
#pragma unroll
    for (int i = 0; i < 4; i++) {
        int qg = q0 + ty * 4 + i;
        float linv = 1.0f / lrow[ty * 4 + i];
#pragma unroll
        for (int j = 0; j < 4; j++) {
            g_O[(size_t)(b * SEQ + qg) * DMODEL + h * DK + tx * 4 + j] = o[i][j] * linv;
        }
    }
}

// ---------------------------------------------------------------------------
extern "C" void kernel_launch(void* const* d_in, const int* in_sizes, int n_in,
                              void* d_out, int out_size) {
    const float* x      = (const float*)d_in[0];
    const int*   pm     = (const int*)  d_in[1];
    const float* mat    = (const float*)d_in[2];
    const float* wq     = (const float*)d_in[3];
    const float* bq     = (const float*)d_in[4];
    const float* wk     = (const float*)d_in[5];
    const float* bk     = (const float*)d_in[6];
    const float* wv     = (const float*)d_in[7];
    const float* bv     = (const float*)d_in[8];
    const float* w_proj = (const float*)d_in[9];
    const float* b_proj = (const float*)d_in[10];
    const float* w_tb1  = (const float*)d_in[11];
    const float* b_tb1  = (const float*)d_in[12];
    const float* w_tb2  = (const float*)d_in[13];
    const float* b_tb2  = (const float*)d_in[14];
    float* out = (float*)d_out;

    cudaFuncSetAttribute(attn_kernel, cudaFuncAttributeMaxDynamicSharedMemorySize, ATTN_SMEM);

    // 1) temporal bias
    bias_kernel<<<(BATCH*SEQ*SEQ + 255) / 256, 256>>>(mat, w_tb1, b_tb1, w_tb2, b_tb2);

    // 2) QKV projections (fused over grid.z)
    gemm_qkv<<<dim3(DMODEL/64, MROWS/64, 3), 256>>>(x, wq, bq, wk, bk, wv, bv);

    // 3) attention
    attn_kernel<<<dim3(SEQ/64, NHEAD, BATCH), 256, ATTN_SMEM>>>(pm);

    // 4) output projection
    gemm_proj<<<dim3(DMODEL/64, MROWS/64), 256>>>(w_proj, b_proj, out);
}

// round 3
// speedup vs baseline: 3.1234x; 3.1234x over previous
#include <cuda_runtime.h>
#include <cuda_fp16.h>
#include <math.h>
#include <stdint.h>

// Problem constants
#define BATCH 8
#define SEQ   512
#define DMODEL 1024
#define NHEAD 16
#define DK    64
#define TBDIM 64
#define SCALE 0.125f
#define NEGINF -1e30f
#define MROWS (BATCH*SEQ)          // 4096

// ---------------------------------------------------------------------------
// Scratch (device globals; no allocation allowed)
// ---------------------------------------------------------------------------
__device__ float  g_Q[MROWS*DMODEL];        // (B,S,D) row-major, head h at col h*64
__device__ float  g_K[MROWS*DMODEL];
__device__ float  g_V[MROWS*DMODEL];
__device__ float  g_Tb[BATCH*SEQ*SEQ];      // temporal bias (B,S,S)
__device__ float  g_O[MROWS*DMODEL];        // attention output (B,S,D)
__device__ __half g_xh[MROWS*DMODEL];       // x in fp16
__device__ __half g_Oh[MROWS*DMODEL];       // attention output in fp16
__device__ __half g_Wq[DMODEL*DMODEL];      // W^T in fp16: [N][K]
__device__ __half g_Wk[DMODEL*DMODEL];
__device__ __half g_Wv[DMODEL*DMODEL];
__device__ __half g_Wp[DMODEL*DMODEL];

// ---------------------------------------------------------------------------
// PTX helpers (sm_80-era only: ldmatrix / mma.sync / cp.async — all legal on
// plain sm_103 target; NO tcgen05)
// ---------------------------------------------------------------------------
__device__ __forceinline__ uint32_t smem_u32(const void* p) {
    uint32_t a;
    asm("{ .reg .u64 t; cvta.to.shared.u64 t, %1; cvt.u32.u64 %0, t; }" : "=r"(a) : "l"(p));
    return a;
}
__device__ __forceinline__ void ldsm_x4(uint32_t (&r)[4], uint32_t addr) {
    asm volatile("ldmatrix.sync.aligned.m8n8.x4.shared.b16 {%0,%1,%2,%3}, [%4];"
        : "=r"(r[0]), "=r"(r[1]), "=r"(r[2]), "=r"(r[3]) : "r"(addr));
}
__device__ __forceinline__ void ldsm_x2(uint32_t (&r)[2], uint32_t addr) {
    asm volatile("ldmatrix.sync.aligned.m8n8.x2.shared.b16 {%0,%1}, [%2];"
        : "=r"(r[0]), "=r"(r[1]) : "r"(addr));
}
__device__ __forceinline__ void mma16816(float (&d)[4], const uint32_t (&a)[4],
                                         const uint32_t (&b)[2]) {
    asm volatile("mma.sync.aligned.m16n8k16.row.col.f32.f16.f16.f32 "
        "{%0,%1,%2,%3}, {%4,%5,%6,%7}, {%8,%9}, {%0,%1,%2,%3};"
        : "+f"(d[0]), "+f"(d[1]), "+f"(d[2]), "+f"(d[3])
        : "r"(a[0]), "r"(a[1]), "r"(a[2]), "r"(a[3]), "r"(b[0]), "r"(b[1]));
}
#define CP_ASYNC16(dst, src) \
    asm volatile("cp.async.cg.shared.global [%0], [%1], 16;" :: "r"(dst), "l"(src) : "memory")
#define CP_COMMIT() asm volatile("cp.async.commit_group;" ::: "memory")
#define CP_WAIT(n)  asm volatile("cp.async.wait_group %0;" :: "n"(n) : "memory")

// ---------------------------------------------------------------------------
// Kernel 1: temporal bias precompute
// ---------------------------------------------------------------------------
__global__ void bias_kernel(const float* __restrict__ mat,
                            const float* __restrict__ w1,
                            const float* __restrict__ b1,
                            const float* __restrict__ w2,
                            const float* __restrict__ b2) {
    __shared__ float sw1[TBDIM], sb1[TBDIM], sw2[TBDIM];
    int tid = threadIdx.x;
    if (tid < TBDIM) { sw1[tid] = w1[tid]; sb1[tid] = b1[tid]; sw2[tid] = w2[tid]; }
    __syncthreads();
    int idx = blockIdx.x * blockDim.x + tid;
    if (idx >= BATCH*SEQ*SEQ) return;
    float t = 1.0f / logf(2.718281828459045f + mat[idx]);
    float acc = b2[0];
#pragma unroll
    for (int j = 0; j < TBDIM; j++) {
        float h = fmaf(t, sw1[j], sb1[j]);
        h = (h >= 0.0f) ? h : 0.2f * h;
        acc = fmaf(h, sw2[j], acc);
    }
    g_Tb[idx] = acc;
}

// ---------------------------------------------------------------------------
// Kernel 2a: fp32 -> fp16 convert (vectorized)
// ---------------------------------------------------------------------------
__global__ void f32tof16(const float* __restrict__ s, __half* __restrict__ d, int n4) {
    int i = blockIdx.x * blockDim.x + threadIdx.x;
    if (i >= n4) return;
    float4 v = ((const float4*)s)[i];
    ((__half2*)d)[2*i]   = __floats2half2_rn(v.x, v.y);
    ((__half2*)d)[2*i+1] = __floats2half2_rn(v.z, v.w);
}

// ---------------------------------------------------------------------------
// Kernel 2b: weight transpose-convert.  Wt[n][k] = (half)W[k][n]
// ---------------------------------------------------------------------------
__global__ void wtrans(const float* __restrict__ w0, const float* __restrict__ w1,
                       const float* __restrict__ w2, const float* __restrict__ w3) {
    int z = blockIdx.z;
    const float* W = (z==0) ? w0 : (z==1) ? w1 : (z==2) ? w2 : w3;
    __half* O      = (z==0) ? g_Wq : (z==1) ? g_Wk : (z==2) ? g_Wv : g_Wp;
    __shared__ float t[32][33];
    int kx = blockIdx.x * 32, ny = blockIdx.y * 32;
    int tx = threadIdx.x, ty = threadIdx.y;
#pragma unroll
    for (int i = 0; i < 4; i++)
        t[ty + i*8][tx] = W[(size_t)(kx + ty + i*8) * DMODEL + ny + tx];
    __syncthreads();
#pragma unroll
    for (int i = 0; i < 4; i++)
        O[(size_t)(ny + ty + i*8) * DMODEL + kx + tx] = __float2half(t[tx][ty + i*8]);
}

// ---------------------------------------------------------------------------
// Kernel 3: HMMA GEMM.  C[m][n] = sum_k A[m][k]*Bt[n][k] + bias[n]
// CTA tile 128x128, BK=32, 256 threads (8 warps, warp tile 64x32),
// cp.async double buffering, ldmatrix + mma.sync m16n8k16.
// Smem rows are 64B (32 halves), XOR-swizzled: chunk ^= (row>>1)&3.
// ---------------------------------------------------------------------------
#define BKH 32          // k per tile (halves)
#define ROWB 64         // bytes per smem row
#define TILEB (128*ROWB)  // 8 KB per operand tile

__global__ void __launch_bounds__(256, 2) gemm_tc(
    const __half* __restrict__ A,
    const __half* __restrict__ B0, const __half* __restrict__ B1, const __half* __restrict__ B2,
    const float* __restrict__ bi0, const float* __restrict__ bi1, const float* __restrict__ bi2,
    float* __restrict__ C0, float* __restrict__ C1, float* __restrict__ C2)
{
    int z = blockIdx.z;
    const __half* Bt   = (z==0) ? B0  : (z==1) ? B1  : B2;
    const float*  bias = (z==0) ? bi0 : (z==1) ? bi1 : bi2;
    float*        C    = (z==0) ? C0  : (z==1) ? C1  : C2;

    __shared__ __align__(128) unsigned char sm[4 * TILEB];  // A0,B0,A1,B1

    int tid  = threadIdx.x;
    int lane = tid & 31;
    int wid  = tid >> 5;
    int wm   = (wid & 1) * 64;      // warp m offset in CTA tile
    int wn   = (wid >> 1) * 32;     // warp n offset
    int m0 = blockIdx.y * 128, n0 = blockIdx.x * 128;

    uint32_t sbase = smem_u32(sm);

    // per-thread load slots: 2 chunks for A, 2 for B, per tile
    // chunk id = tid + 256*i ; row = id>>2, c = id&3
    int lr0 = (tid      ) >> 2, lc0 = (tid      ) & 3;
    int lr1 = (tid + 256) >> 2, lc1 = (tid + 256) & 3;
    uint32_t sw0 = lr0 * ROWB + ((lc0 ^ ((lr0 >> 1) & 3)) * 16);
    uint32_t sw1 = lr1 * ROWB + ((lc1 ^ ((lr1 >> 1) & 3)) * 16);

    const __half* gA = A  + (size_t)(m0 + lr0) * DMODEL + lc0 * 8;
    const __half* gA1= A  + (size_t)(m0 + lr1) * DMODEL + lc1 * 8;
    const __half* gB = Bt + (size_t)(n0 + lr0) * DMODEL + lc0 * 8;
    const __half* gB1= Bt + (size_t)(n0 + lr1) * DMODEL + lc1 * 8;

    float acc[4][4][4] = {};   // [mf][nf][reg]

    // prefetch tile 0 into buffer 0
    {
        uint32_t a0 = sbase + sw0, a1 = sbase + sw1;
        uint32_t b0 = sbase + TILEB + sw0, b1 = sbase + TILEB + sw1;
        CP_ASYNC16(a0, gA);  CP_ASYNC16(a1, gA1);
        CP_ASYNC16(b0, gB);  CP_ASYNC16(b1, gB1);
        CP_COMMIT();
    }

    const int NKT = DMODEL / BKH;   // 32
    for (int kt = 0; kt < NKT; kt++) {
        int cur = kt & 1;
        if (kt + 1 < NKT) {
            int nxt = (kt + 1) & 1;
            uint32_t ab = sbase + nxt * 2 * TILEB;
            int koff = (kt + 1) * BKH;
            CP_ASYNC16(ab + sw0,         gA  + koff);
            CP_ASYNC16(ab + sw1,         gA1 + koff);
            CP_ASYNC16(ab + TILEB + sw0, gB  + koff);
            CP_ASYNC16(ab + TILEB + sw1, gB1 + koff);
            CP_COMMIT();
            CP_WAIT(1);
        } else {
            CP_WAIT(0);
        }
        __syncthreads();

        uint32_t aBase = sbase + cur * 2 * TILEB;
        uint32_t bBase = aBase + TILEB;

#pragma unroll
        for (int ks = 0; ks < 2; ks++) {
            // A fragments: 4 m-frags of 16 rows
            uint32_t af[4][4];
#pragma unroll
            for (int mf = 0; mf < 4; mf++) {
                int row = wm + mf * 16 + (lane & 15);
                int ch  = 2 * ks + (lane >> 4);
                uint32_t ad = aBase + row * ROWB + ((ch ^ ((row >> 1) & 3)) * 16);
                ldsm_x4(af[mf], ad);
            }
            // B fragments: 4 n-frags of 8 rows
            uint32_t bf[4][2];
#pragma unroll
            for (int nf = 0; nf < 4; nf++) {
                int row = wn + nf * 8 + (lane & 7);
                int ch  = 2 * ks + ((lane >> 3) & 1);
                uint32_t bd = bBase + row * ROWB + ((ch ^ ((row >> 1) & 3)) * 16);
                ldsm_x2(bf[nf], bd);
            }
#pragma unroll
            for (int mf = 0; mf < 4; mf++)
#pragma unroll
                for (int nf = 0; nf < 4; nf++)
                    mma16816(acc[mf][nf], af[mf], bf[nf]);
        }
        __syncthreads();
    }

    // Epilogue: thread (g = lane>>2, t = lane&3)
    int g = lane >> 2, t = lane & 3;
#pragma unroll
    for (int mf = 0; mf < 4; mf++) {
        int r0 = m0 + wm + mf * 16 + g;
#pragma unroll
        for (int nf = 0; nf < 4; nf++) {
            int c = n0 + wn + nf * 8 + t * 2;
            float bx = __ldg(&bias[c]), by = __ldg(&bias[c + 1]);
            float2 v0 = { acc[mf][nf][0] + bx, acc[mf][nf][1] + by };
            float2 v1 = { acc[mf][nf][2] + bx, acc[mf][nf][3] + by };
            *(float2*)&C[(size_t)r0 * DMODEL + c]       = v0;
            *(float2*)&C[(size_t)(r0 + 8) * DMODEL + c] = v1;
        }
    }
}

// ---------------------------------------------------------------------------
// Kernel 4: causal flash attention (fp32), Q/K/V in (B,S,D) layout
// ---------------------------------------------------------------------------
#define SPAD 68
#define ATTN_SMEM ((4*64*SPAD + 3*64) * 4)

__global__ void attn_kernel(const int* __restrict__ pm) {
    extern __shared__ float smf[];
    float* Qs   = smf;
    float* KsT  = Qs  + 64 * SPAD;
    float* Vs   = KsT + 64 * SPAD;
    float* Ss   = Vs  + 64 * SPAD;
    float* mrow = Ss  + 64 * SPAD;
    float* lrow = mrow + 64;
    float* crow = lrow + 64;

    int qt = blockIdx.x;
    int h  = blockIdx.y;
    int b  = blockIdx.z;
    int tid = threadIdx.x;
    int tx = tid & 15, ty = tid >> 4;

    const float* Qg = g_Q + (size_t)b * SEQ * DMODEL + h * DK;
    const float* Kg = g_K + (size_t)b * SEQ * DMODEL + h * DK;
    const float* Vg = g_V + (size_t)b * SEQ * DMODEL + h * DK;
    const float* Tbb = g_Tb + (size_t)b * SEQ * SEQ;
    int q0 = qt * 64;

    {
        int r = tid >> 4, c4 = tid & 15;
#pragma unroll
        for (int p = 0; p < 4; p++) {
            int rr = r + p * 16;
            float4 v = *(const float4*)&Qg[(size_t)(q0 + rr) * DMODEL + c4 * 4];
            v.x *= SCALE; v.y *= SCALE; v.z *= SCALE; v.w *= SCALE;
            *(float4*)&Qs[rr * SPAD + c4 * 4] = v;
        }
    }
    if (tid < 64) { mrow[tid] = NEGINF; lrow[tid] = 0.0f; }

    float o[4][4] = {};

    for (int kt = 0; kt <= qt; kt++) {
        {
            int r = tid >> 4, c4 = tid & 15;
#pragma unroll
            for (int p = 0; p < 4; p++) {
                int rr = r + p * 16;
                float4 kv = *(const float4*)&Kg[(size_t)(kt * 64 + rr) * DMODEL + c4 * 4];
                KsT[(c4*4 + 0) * SPAD + rr] = kv.x;
                KsT[(c4*4 + 1) * SPAD + rr] = kv.y;
                KsT[(c4*4 + 2) * SPAD + rr] = kv.z;
                KsT[(c4*4 + 3) * SPAD + rr] = kv.w;
                *(float4*)&Vs[rr * SPAD + c4 * 4] =
                    *(const float4*)&Vg[(size_t)(kt * 64 + rr) * DMODEL + c4 * 4];
            }
        }
        __syncthreads();

        float s[4][4] = {};
#pragma unroll
        for (int d = 0; d < 64; d++) {
            float a0 = Qs[(ty*4 + 0) * SPAD + d];
            float a1 = Qs[(ty*4 + 1) * SPAD + d];
            float a2 = Qs[(ty*4 + 2) * SPAD + d];
            float a3 = Qs[(ty*4 + 3) * SPAD + d];
            float4 b4 = *(const float4*)&KsT[d * SPAD + tx * 4];
            s[0][0] = fmaf(a0, b4.x, s[0][0]); s[0][1] = fmaf(a0, b4.y, s[0][1]);
            s[0][2] = fmaf(a0, b4.z, s[0][2]); s[0][3] = fmaf(a0, b4.w, s[0][3]);
            s[1][0] = fmaf(a1, b4.x, s[1][0]); s[1][1] = fmaf(a1, b4.y, s[1][1]);
            s[1][2] = fmaf(a1, b4.z, s[1][2]); s[1][3] = fmaf(a1, b4.w, s[1][3]);
            s[2][0] = fmaf(a2, b4.x, s[2][0]); s[2][1] = fmaf(a2, b4.y, s[2][1]);
            s[2][2] = fmaf(a2, b4.z, s[2][2]); s[2][3] = fmaf(a2, b4.w, s[2][3]);
            s[3][0] = fmaf(a3, b4.x, s[3][0]); s[3][1] = fmaf(a3, b4.y, s[3][1]);
            s[3][2] = fmaf(a3, b4.z, s[3][2]); s[3][3] = fmaf(a3, b4.w, s[3][3]);
        }

#pragma unroll
        for (int i = 0; i < 4; i++) {
            int qg = q0 + ty * 4 + i;
            const float* tb = &Tbb[(size_t)qg * SEQ + kt * 64 + tx * 4];
#pragma unroll
            for (int j = 0; j < 4; j++) {
                int kg = kt * 64 + tx * 4 + j;
                float v = s[i][j] + tb[j];
                if (kg > qg || pm[b * SEQ + kg] == 0) v = NEGINF;
                Ss[(ty*4 + i) * SPAD + tx * 4 + j] = v;
            }
        }
        __syncthreads();

        {
            int row = tid >> 2, gg = tid & 3;
            float* sr = &Ss[row * SPAD + gg * 16];
            float mx = NEGINF;
#pragma unroll
            for (int k = 0; k < 16; k++) mx = fmaxf(mx, sr[k]);
            mx = fmaxf(mx, __shfl_xor_sync(0xffffffffu, mx, 1));
            mx = fmaxf(mx, __shfl_xor_sync(0xffffffffu, mx, 2));
            float mold = mrow[row];
            float mnew = fmaxf(mold, mx);
            float corr = __expf(mold - mnew);
            float sum = 0.0f;
#pragma unroll
            for (int k = 0; k < 16; k++) {
                float p = __expf(sr[k] - mnew);
                sr[k] = p;
                sum += p;
            }
            sum += __shfl_xor_sync(0xffffffffu, sum, 1);
            sum += __shfl_xor_sync(0xffffffffu, sum, 2);
            if (gg == 0) {
                lrow[row] = lrow[row] * corr + sum;
                mrow[row] = mnew;
                crow[row] = corr;
            }
        }
        __syncthreads();

        float c0 = crow[ty*4 + 0], c1 = crow[ty*4 + 1];
        float c2 = crow[ty*4 + 2], c3 = crow[ty*4 + 3];
#pragma unroll
        for (int j = 0; j < 4; j++) {
            o[0][j] *= c0; o[1][j] *= c1; o[2][j] *= c2; o[3][j] *= c3;
        }
#pragma unroll
        for (int kk = 0; kk < 64; kk++) {
            float a0 = Ss[(ty*4 + 0) * SPAD + kk];
            float a1 = Ss[(ty*4 + 1) * SPAD + kk];
            float a2 = Ss[(ty*4 + 2) * SPAD + kk];
            float a3 = Ss[(ty*4 + 3) * SPAD + kk];
            float4 b4 = *(const float4*)&Vs[kk * SPAD + tx * 4];
            o[0][0] = fmaf(a0, b4.x, o[0][0]); o[0][1] = fmaf(a0, b4.y, o[0][1]);
            o[0][2] = fmaf(a0, b4.z, o[0][2]); o[0][3] = fmaf(a0, b4.w, o[0][3]);
            o[1][0] = fmaf(a1, b4.x, o[1][0]); o[1][1] = fmaf(a1, b4.y, o[1][1]);
            o[1][2] = fmaf(a1, b4.z, o[1][2]); o[1][3] = fmaf(a1, b4.w, o[1][3]);
            o[2][0] = fmaf(a2, b4.x, o[2][0]); o[2][1] = fmaf(a2, b4.y, o[2][1]);
            o[2][2] = fmaf(a2, b4.z, o[2][2]); o[2][3] = fmaf(a2, b4.w, o[2][3]);
            o[3][0] = fmaf(a3, b4.x, o[3][0]); o[3][1] = fmaf(a3, b4.y, o[3][1]);
            o[3][2] = fmaf(a3, b4.z, o[3][2]); o[3][3] = fmaf(a3, b4.w, o[3][3]);
        }
        __syncthreads();
    }

#pragma unroll
    for (int i = 0; i < 4; i++) {
        int qg = q0 + ty * 4 + i;
        float linv = 1.0f / lrow[ty * 4 + i];
#pragma unroll
        for (int j = 0; j < 4; j++) {
            g_O[(size_t)(b * SEQ + qg) * DMODEL + h * DK + tx * 4 + j] = o[i][j] * linv;
        }
    }
}

// ---------------------------------------------------------------------------
extern "C" void kernel_launch(void* const* d_in, const int* in_sizes, int n_in,
                              void* d_out, int out_size) {
    const float* x      = (const float*)d_in[0];
    const int*   pm     = (const int*)  d_in[1];
    const float* mat    = (const float*)d_in[2];
    const float* wq     = (const float*)d_in[3];
    const float* bq     = (const float*)d_in[4];
    const float* wk     = (const float*)d_in[5];
    const float* bk     = (const float*)d_in[6];
    const float* wv     = (const float*)d_in[7];
    const float* bv     = (const float*)d_in[8];
    const float* w_proj = (const float*)d_in[9];
    const float* b_proj = (const float*)d_in[10];
    const float* w_tb1  = (const float*)d_in[11];
    const float* b_tb1  = (const float*)d_in[12];
    const float* w_tb2  = (const float*)d_in[13];
    const float* b_tb2  = (const float*)d_in[14];
    float* out = (float*)d_out;

    cudaFuncSetAttribute(attn_kernel, cudaFuncAttributeMaxDynamicSharedMemorySize, ATTN_SMEM);

    __half *xh, *Oh, *Wq, *Wk, *Wv, *Wp;
    float  *Q, *K, *V, *O;
    cudaGetSymbolAddress((void**)&xh, g_xh);
    cudaGetSymbolAddress((void**)&Oh, g_Oh);
    cudaGetSymbolAddress((void**)&Wq, g_Wq);
    cudaGetSymbolAddress((void**)&Wk, g_Wk);
    cudaGetSymbolAddress((void**)&Wv, g_Wv);
    cudaGetSymbolAddress((void**)&Wp, g_Wp);
    cudaGetSymbolAddress((void**)&Q,  g_Q);
    cudaGetSymbolAddress((void**)&K,  g_K);
    cudaGetSymbolAddress((void**)&V,  g_V);
    cudaGetSymbolAddress((void**)&O,  g_O);

    // 1) temporal bias
    bias_kernel<<<(BATCH*SEQ*SEQ + 255) / 256, 256>>>(mat, w_tb1, b_tb1, w_tb2, b_tb2);

    // 2) converts
    f32tof16<<<(MROWS*DMODEL/4 + 255)/256, 256>>>(x, xh, MROWS*DMODEL/4);
    wtrans<<<dim3(32, 32, 4), dim3(32, 8)>>>(wq, wk, wv, w_proj);

    // 3) QKV projections (HMMA)
    gemm_tc<<<dim3(DMODEL/128, MROWS/128, 3), 256>>>(
        xh, Wq, Wk, Wv, bq, bk, bv, Q, K, V);

    // 4) attention
    attn_kernel<<<dim3(SEQ/64, NHEAD, BATCH), 256, ATTN_SMEM>>>(pm);

    // 5) attention output -> fp16
    f32tof16<<<(MROWS*DMODEL/4 + 255)/256, 256>>>(O, Oh, MROWS*DMODEL/4);

    // 6) output projection (HMMA)
    gemm_tc<<<dim3(DMODEL/128, MROWS/128, 1), 256>>>(
        Oh, Wp, Wp, Wp, b_proj, b_proj, b_proj, out, out, out);
}

// round 4
// speedup vs baseline: 5.8061x; 1.8589x over previous
#include <cuda_runtime.h>
#include <cuda_fp16.h>
#include <math.h>
#include <stdint.h>

// Problem constants
#define BATCH 8
#define SEQ   512
#define DMODEL 1024
#define NHEAD 16
#define DK    64
#define TBDIM 64
#define SCALE 0.125f
#define NEGINF -1e30f
#define MROWS (BATCH*SEQ)          // 4096

// ---------------------------------------------------------------------------
// Scratch (device globals)
// ---------------------------------------------------------------------------
__device__ float  g_Tb[BATCH*SEQ*SEQ];      // temporal bias (B,S,S) fp32
__device__ __half g_xh[MROWS*DMODEL];       // x in fp16
__device__ __half g_Qh[MROWS*DMODEL];       // Q (B,S,D) fp16, head h at col h*64
__device__ __half g_Kh[MROWS*DMODEL];
__device__ __half g_Vh[MROWS*DMODEL];
__device__ __half g_Oh[MROWS*DMODEL];       // attention output fp16
__device__ __half g_Wq[DMODEL*DMODEL];      // W^T fp16: [N][K]
__device__ __half g_Wk[DMODEL*DMODEL];
__device__ __half g_Wv[DMODEL*DMODEL];
__device__ __half g_Wp[DMODEL*DMODEL];

// ---------------------------------------------------------------------------
// PTX helpers (sm_80-era: ldmatrix / mma.sync / cp.async)
// ---------------------------------------------------------------------------
__device__ __forceinline__ uint32_t smem_u32(const void* p) {
    uint32_t a;
    asm("{ .reg .u64 t; cvta.to.shared.u64 t, %1; cvt.u32.u64 %0, t; }" : "=r"(a) : "l"(p));
    return a;
}
__device__ __forceinline__ void ldsm_x4(uint32_t (&r)[4], uint32_t addr) {
    asm volatile("ldmatrix.sync.aligned.m8n8.x4.shared.b16 {%0,%1,%2,%3}, [%4];"
        : "=r"(r[0]), "=r"(r[1]), "=r"(r[2]), "=r"(r[3]) : "r"(addr));
}
__device__ __forceinline__ void ldsm_x2(uint32_t (&r)[2], uint32_t addr) {
    asm volatile("ldmatrix.sync.aligned.m8n8.x2.shared.b16 {%0,%1}, [%2];"
        : "=r"(r[0]), "=r"(r[1]) : "r"(addr));
}
__device__ __forceinline__ void ldsm_x2t(uint32_t (&r)[2], uint32_t addr) {
    asm volatile("ldmatrix.sync.aligned.m8n8.x2.trans.shared.b16 {%0,%1}, [%2];"
        : "=r"(r[0]), "=r"(r[1]) : "r"(addr));
}
__device__ __forceinline__ void mma16816(float (&d)[4], const uint32_t (&a)[4],
                                         const uint32_t (&b)[2]) {
    asm volatile("mma.sync.aligned.m16n8k16.row.col.f32.f16.f16.f32 "
        "{%0,%1,%2,%3}, {%4,%5,%6,%7}, {%8,%9}, {%0,%1,%2,%3};"
        : "+f"(d[0]), "+f"(d[1]), "+f"(d[2]), "+f"(d[3])
        : "r"(a[0]), "r"(a[1]), "r"(a[2]), "r"(a[3]), "r"(b[0]), "r"(b[1]));
}
__device__ __forceinline__ uint32_t packh2(float a, float b) {
    __half2 h = __floats2half2_rn(a, b);
    return *(uint32_t*)&h;
}
#define CP_ASYNC16(dst, src) \
    asm volatile("cp.async.cg.shared.global [%0], [%1], 16;" :: "r"(dst), "l"(src) : "memory")
#define CP_COMMIT() asm volatile("cp.async.commit_group;" ::: "memory")
#define CP_WAIT(n)  asm volatile("cp.async.wait_group %0;" :: "n"(n) : "memory")

// ---------------------------------------------------------------------------
// Kernel 1: temporal bias precompute
// ---------------------------------------------------------------------------
__global__ void bias_kernel(const float* __restrict__ mat,
                            const float* __restrict__ w1,
                            const float* __restrict__ b1,
                            const float* __restrict__ w2,
                            const float* __restrict__ b2) {
    __shared__ float sw1[TBDIM], sb1[TBDIM], sw2[TBDIM];
    int tid = threadIdx.x;
    if (tid < TBDIM) { sw1[tid] = w1[tid]; sb1[tid] = b1[tid]; sw2[tid] = w2[tid]; }
    __syncthreads();
    int idx = blockIdx.x * blockDim.x + tid;
    if (idx >= BATCH*SEQ*SEQ) return;
    float t = 1.0f / logf(2.718281828459045f + mat[idx]);
    float acc = b2[0];
#pragma unroll
    for (int j = 0; j < TBDIM; j++) {
        float h = fmaf(t, sw1[j], sb1[j]);
        h = (h >= 0.0f) ? h : 0.2f * h;
        acc = fmaf(h, sw2[j], acc);
    }
    g_Tb[idx] = acc;
}

// ---------------------------------------------------------------------------
// Kernel 2a: fp32 -> fp16 convert
// ---------------------------------------------------------------------------
__global__ void f32tof16(const float* __restrict__ s, __half* __restrict__ d, int n4) {
    int i = blockIdx.x * blockDim.x + threadIdx.x;
    if (i >= n4) return;
    float4 v = ((const float4*)s)[i];
    ((__half2*)d)[2*i]   = __floats2half2_rn(v.x, v.y);
    ((__half2*)d)[2*i+1] = __floats2half2_rn(v.z, v.w);
}

// ---------------------------------------------------------------------------
// Kernel 2b: weight transpose-convert.  Wt[n][k] = (half)W[k][n]
// ---------------------------------------------------------------------------
__global__ void wtrans(const float* __restrict__ w0, const float* __restrict__ w1,
                       const float* __restrict__ w2, const float* __restrict__ w3) {
    int z = blockIdx.z;
    const float* W = (z==0) ? w0 : (z==1) ? w1 : (z==2) ? w2 : w3;
    __half* O      = (z==0) ? g_Wq : (z==1) ? g_Wk : (z==2) ? g_Wv : g_Wp;
    __shared__ float t[32][33];
    int kx = blockIdx.x * 32, ny = blockIdx.y * 32;
    int tx = threadIdx.x, ty = threadIdx.y;
#pragma unroll
    for (int i = 0; i < 4; i++)
        t[ty + i*8][tx] = W[(size_t)(kx + ty + i*8) * DMODEL + ny + tx];
    __syncthreads();
#pragma unroll
    for (int i = 0; i < 4; i++)
        O[(size_t)(ny + ty + i*8) * DMODEL + kx + tx] = __float2half(t[tx][ty + i*8]);
}

// ---------------------------------------------------------------------------
// Kernel 3: HMMA GEMM.  C[m][n] = sum_k A[m][k]*Bt[n][k] + bias[n]
// Output type templated: fp16 for QKV, fp32 for final projection.
// ---------------------------------------------------------------------------
#define BKH 32
#define ROWB 64
#define TILEB (128*ROWB)

__device__ __forceinline__ void store2(float* C, size_t idx, float a, float b) {
    float2 v = {a, b}; *(float2*)&C[idx] = v;
}
__device__ __forceinline__ void store2(__half* C, size_t idx, float a, float b) {
    *(__half2*)&C[idx] = __floats2half2_rn(a, b);
}

template <typename TOUT>
__global__ void __launch_bounds__(256, 2) gemm_tc(
    const __half* __restrict__ A,
    const __half* __restrict__ B0, const __half* __restrict__ B1, const __half* __restrict__ B2,
    const float* __restrict__ bi0, const float* __restrict__ bi1, const float* __restrict__ bi2,
    TOUT* __restrict__ C0, TOUT* __restrict__ C1, TOUT* __restrict__ C2)
{
    int z = blockIdx.z;
    const __half* Bt   = (z==0) ? B0  : (z==1) ? B1  : B2;
    const float*  bias = (z==0) ? bi0 : (z==1) ? bi1 : bi2;
    TOUT*         C    = (z==0) ? C0  : (z==1) ? C1  : C2;

    __shared__ __align__(128) unsigned char sm[4 * TILEB];

    int tid  = threadIdx.x;
    int lane = tid & 31;
    int wid  = tid >> 5;
    int wm   = (wid & 1) * 64;
    int wn   = (wid >> 1) * 32;
    int m0 = blockIdx.y * 128, n0 = blockIdx.x * 128;

    uint32_t sbase = smem_u32(sm);

    int lr0 = (tid      ) >> 2, lc0 = (tid      ) & 3;
    int lr1 = (tid + 256) >> 2, lc1 = (tid + 256) & 3;
    uint32_t sw0 = lr0 * ROWB + ((lc0 ^ ((lr0 >> 1) & 3)) * 16);
    uint32_t sw1 = lr1 * ROWB + ((lc1 ^ ((lr1 >> 1) & 3)) * 16);

    const __half* gA = A  + (size_t)(m0 + lr0) * DMODEL + lc0 * 8;
    const __half* gA1= A  + (size_t)(m0 + lr1) * DMODEL + lc1 * 8;
    const __half* gB = Bt + (size_t)(n0 + lr0) * DMODEL + lc0 * 8;
    const __half* gB1= Bt + (size_t)(n0 + lr1) * DMODEL + lc1 * 8;

    float acc[4][4][4] = {};

    {
        CP_ASYNC16(sbase + sw0, gA);          CP_ASYNC16(sbase + sw1, gA1);
        CP_ASYNC16(sbase + TILEB + sw0, gB);  CP_ASYNC16(sbase + TILEB + sw1, gB1);
        CP_COMMIT();
    }

    const int NKT = DMODEL / BKH;
    for (int kt = 0; kt < NKT; kt++) {
        int cur = kt & 1;
        if (kt + 1 < NKT) {
            int nxt = (kt + 1) & 1;
            uint32_t ab = sbase + nxt * 2 * TILEB;
            int koff = (kt + 1) * BKH;
            CP_ASYNC16(ab + sw0,         gA  + koff);
            CP_ASYNC16(ab + sw1,         gA1 + koff);
            CP_ASYNC16(ab + TILEB + sw0, gB  + koff);
            CP_ASYNC16(ab + TILEB + sw1, gB1 + koff);
            CP_COMMIT();
            CP_WAIT(1);
        } else {
            CP_WAIT(0);
        }
        __syncthreads();

        uint32_t aBase = sbase + cur * 2 * TILEB;
        uint32_t bBase = aBase + TILEB;

#pragma unroll
        for (int ks = 0; ks < 2; ks++) {
            uint32_t af[4][4];
#pragma unroll
            for (int mf = 0; mf < 4; mf++) {
                int row = wm + mf * 16 + (lane & 15);
                int ch  = 2 * ks + (lane >> 4);
                ldsm_x4(af[mf], aBase + row * ROWB + ((ch ^ ((row >> 1) & 3)) * 16));
            }
            uint32_t bf[4][2];
#pragma unroll
            for (int nf = 0; nf < 4; nf++) {
                int row = wn + nf * 8 + (lane & 7);
                int ch  = 2 * ks + ((lane >> 3) & 1);
                ldsm_x2(bf[nf], bBase + row * ROWB + ((ch ^ ((row >> 1) & 3)) * 16));
            }
#pragma unroll
            for (int mf = 0; mf < 4; mf++)
#pragma unroll
                for (int nf = 0; nf < 4; nf++)
                    mma16816(acc[mf][nf], af[mf], bf[nf]);
        }
        __syncthreads();
    }

    int g = lane >> 2, t = lane & 3;
#pragma unroll
    for (int mf = 0; mf < 4; mf++) {
        int r0 = m0 + wm + mf * 16 + g;
#pragma unroll
        for (int nf = 0; nf < 4; nf++) {
            int c = n0 + wn + nf * 8 + t * 2;
            float bx = __ldg(&bias[c]), by = __ldg(&bias[c + 1]);
            store2(C, (size_t)r0 * DMODEL + c,       acc[mf][nf][0] + bx, acc[mf][nf][1] + by);
            store2(C, (size_t)(r0 + 8) * DMODEL + c, acc[mf][nf][2] + bx, acc[mf][nf][3] + by);
        }
    }
}

// ---------------------------------------------------------------------------
// Kernel 4: HMMA causal flash attention.
// 128 threads (4 warps), block = (q-tile 64, head, batch). Warp owns 16 q rows.
// S = Q K^T via mma m16n8k16 (K natural layout = Bt operand).
// P repacked reg->reg into A frags; P·V via ldmatrix.x2.trans on V natural layout.
// K/V/pm double-buffered with cp.async. Output written fp16 to g_Oh.
// Smem rows: 64 halves = 128B = 8 chunks; swizzle chunk ^= row&7.
// ---------------------------------------------------------------------------
__global__ void __launch_bounds__(128) attn_hmma(const int* __restrict__ pm) {
    __shared__ __align__(128) __half Qs[64*64];
    __shared__ __align__(128) __half Ks[2][64*64];
    __shared__ __align__(128) __half Vs[2][64*64];
    __shared__ int spm[2][64];

    int qt = blockIdx.x, h = blockIdx.y, b = blockIdx.z;
    int tid = threadIdx.x, lane = tid & 31, wid = tid >> 5;
    int wrow = wid * 16;
    int q0 = qt * 64;
    int g = lane >> 2, t = lane & 3;

    const __half* Qg = g_Qh + (size_t)b * SEQ * DMODEL + h * DK;
    const __half* Kg = g_Kh + (size_t)b * SEQ * DMODEL + h * DK;
    const __half* Vg = g_Vh + (size_t)b * SEQ * DMODEL + h * DK;
    const float* Tbb = g_Tb + (size_t)b * SEQ * SEQ;

    uint32_t qb  = smem_u32(Qs);
    uint32_t kb_[2] = { smem_u32(Ks[0]), smem_u32(Ks[1]) };
    uint32_t vb_[2] = { smem_u32(Vs[0]), smem_u32(Vs[1]) };

    // Q tile load (once)
#pragma unroll
    for (int i = 0; i < 4; i++) {
        int id = tid + i * 128;
        int rr = id >> 3, c = id & 7;
        uint32_t sw = rr * 128 + ((c ^ (rr & 7)) * 16);
        CP_ASYNC16(qb + sw, Qg + (size_t)(q0 + rr) * DMODEL + c * 8);
    }
    // K/V/pm tile 0
#pragma unroll
    for (int i = 0; i < 4; i++) {
        int id = tid + i * 128;
        int rr = id >> 3, c = id & 7;
        uint32_t sw = rr * 128 + ((c ^ (rr & 7)) * 16);
        CP_ASYNC16(kb_[0] + sw, Kg + (size_t)rr * DMODEL + c * 8);
        CP_ASYNC16(vb_[0] + sw, Vg + (size_t)rr * DMODEL + c * 8);
    }
    if (tid < 16)
        CP_ASYNC16(smem_u32(spm[0]) + tid * 16, pm + b * SEQ + tid * 4);
    CP_COMMIT();

    float m0 = NEGINF, m1 = NEGINF, l0 = 0.0f, l1 = 0.0f;
    float o[8][4] = {};
    int qgl0 = q0 + wrow + g;
    int qgl1 = qgl0 + 8;

    for (int kt = 0; kt <= qt; kt++) {
        int cur = kt & 1;
        if (kt < qt) {
            int nxt = (kt + 1) & 1;
#pragma unroll
            for (int i = 0; i < 4; i++) {
                int id = tid + i * 128;
                int rr = id >> 3, c = id & 7;
                uint32_t sw = rr * 128 + ((c ^ (rr & 7)) * 16);
                CP_ASYNC16(kb_[nxt] + sw, Kg + (size_t)((kt+1)*64 + rr) * DMODEL + c * 8);
                CP_ASYNC16(vb_[nxt] + sw, Vg + (size_t)((kt+1)*64 + rr) * DMODEL + c * 8);
            }
            if (tid < 16)
                CP_ASYNC16(smem_u32(spm[nxt]) + tid * 16, pm + b * SEQ + (kt+1)*64 + tid * 4);
            CP_COMMIT();
            CP_WAIT(1);
        } else {
            CP_WAIT(0);
        }
        __syncthreads();

        uint32_t kb = kb_[cur], vb = vb_[cur];
        const int* pmc = spm[cur];

        // ---- S = Q K^T ----
        float s[8][4] = {};
#pragma unroll
        for (int ks = 0; ks < 4; ks++) {
            uint32_t a[4];
            {
                int row = wrow + (lane & 15);
                int ch  = ks * 2 + (lane >> 4);
                ldsm_x4(a, qb + row * 128 + ((ch ^ (row & 7)) * 16));
            }
#pragma unroll
            for (int nf = 0; nf < 8; nf++) {
                uint32_t bfr[2];
                int row = nf * 8 + (lane & 7);
                int ch  = ks * 2 + ((lane >> 3) & 1);
                ldsm_x2(bfr, kb + row * 128 + ((ch ^ (row & 7)) * 16));
                mma16816(s[nf], a, bfr);
            }
        }

        // ---- scale + bias + masks + row max ----
        float mx0 = m0, mx1 = m1;
#pragma unroll
        for (int nf = 0; nf < 8; nf++) {
            int coll = nf * 8 + t * 2;
            int kg = kt * 64 + coll;
            float2 tb0 = *(const float2*)&Tbb[(size_t)qgl0 * SEQ + kg];
            float2 tb1 = *(const float2*)&Tbb[(size_t)qgl1 * SEQ + kg];
            float v00 = fmaf(s[nf][0], SCALE, tb0.x);
            float v01 = fmaf(s[nf][1], SCALE, tb0.y);
            float v10 = fmaf(s[nf][2], SCALE, tb1.x);
            float v11 = fmaf(s[nf][3], SCALE, tb1.y);
            bool z0 = (pmc[coll] == 0), z1 = (pmc[coll + 1] == 0);
            if (z0 || kg     > qgl0) v00 = NEGINF;
            if (z1 || kg + 1 > qgl0) v01 = NEGINF;
            if (z0 || kg     > qgl1) v10 = NEGINF;
            if (z1 || kg + 1 > qgl1) v11 = NEGINF;
            s[nf][0] = v00; s[nf][1] = v01; s[nf][2] = v10; s[nf][3] = v11;
            mx0 = fmaxf(mx0, fmaxf(v00, v01));
            mx1 = fmaxf(mx1, fmaxf(v10, v11));
        }
        mx0 = fmaxf(mx0, __shfl_xor_sync(0xffffffffu, mx0, 1));
        mx0 = fmaxf(mx0, __shfl_xor_sync(0xffffffffu, mx0, 2));
        mx1 = fmaxf(mx1, __shfl_xor_sync(0xffffffffu, mx1, 1));
        mx1 = fmaxf(mx1, __shfl_xor_sync(0xffffffffu, mx1, 2));

        float corr0 = __expf(m0 - mx0);
        float corr1 = __expf(m1 - mx1);
        m0 = mx0; m1 = mx1;

        // ---- exponentiate, row sums ----
        float sum0 = 0.0f, sum1 = 0.0f;
#pragma unroll
        for (int nf = 0; nf < 8; nf++) {
            float p00 = __expf(s[nf][0] - mx0);
            float p01 = __expf(s[nf][1] - mx0);
            float p10 = __expf(s[nf][2] - mx1);
            float p11 = __expf(s[nf][3] - mx1);
            s[nf][0] = p00; s[nf][1] = p01; s[nf][2] = p10; s[nf][3] = p11;
            sum0 += p00 + p01;
            sum1 += p10 + p11;
        }
        sum0 += __shfl_xor_sync(0xffffffffu, sum0, 1);
        sum0 += __shfl_xor_sync(0xffffffffu, sum0, 2);
        sum1 += __shfl_xor_sync(0xffffffffu, sum1, 1);
        sum1 += __shfl_xor_sync(0xffffffffu, sum1, 2);
        l0 = l0 * corr0 + sum0;
        l1 = l1 * corr1 + sum1;

        // ---- rescale O, pack P into A frags ----
#pragma unroll
        for (int nf = 0; nf < 8; nf++) {
            o[nf][0] *= corr0; o[nf][1] *= corr0;
            o[nf][2] *= corr1; o[nf][3] *= corr1;
        }
        uint32_t pa[4][4];
#pragma unroll
        for (int kk = 0; kk < 4; kk++) {
            pa[kk][0] = packh2(s[2*kk][0],   s[2*kk][1]);
            pa[kk][1] = packh2(s[2*kk][2],   s[2*kk][3]);
            pa[kk][2] = packh2(s[2*kk+1][0], s[2*kk+1][1]);
            pa[kk][3] = packh2(s[2*kk+1][2], s[2*kk+1][3]);
        }

        // ---- O += P V ----
#pragma unroll
        for (int kk = 0; kk < 4; kk++) {
#pragma unroll
            for (int nf = 0; nf < 8; nf++) {
                uint32_t bfr[2];
                int row = kk * 16 + (lane & 7) + ((lane >> 3) & 1) * 8;
                ldsm_x2t(bfr, vb + row * 128 + ((nf ^ (row & 7)) * 16));
                mma16816(o[nf], pa[kk], bfr);
            }
        }
        __syncthreads();
    }

    // ---- normalize + write fp16 output ----
    float inv0 = 1.0f / l0, inv1 = 1.0f / l1;
    __half* Og = g_Oh + (size_t)b * SEQ * DMODEL + h * DK;
#pragma unroll
    for (int nf = 0; nf < 8; nf++) {
        int coll = nf * 8 + t * 2;
        *(__half2*)&Og[(size_t)(q0 + wrow + g) * DMODEL + coll] =
            __floats2half2_rn(o[nf][0] * inv0, o[nf][1] * inv0);
        *(__half2*)&Og[(size_t)(q0 + wrow + g + 8) * DMODEL + coll] =
            __floats2half2_rn(o[nf][2] * inv1, o[nf][3] * inv1);
    }
}

// ---------------------------------------------------------------------------
extern "C" void kernel_launch(void* const* d_in, const int* in_sizes, int n_in,
                              void* d_out, int out_size) {
    const float* x      = (const float*)d_in[0];
    const int*   pm     = (const int*)  d_in[1];
    const float* mat    = (const float*)d_in[2];
    const float* wq     = (const float*)d_in[3];
    const float* bq     = (const float*)d_in[4];
    const float* wk     = (const float*)d_in[5];
    const float* bk     = (const float*)d_in[6];
    const float* wv     = (const float*)d_in[7];
    const float* bv     = (const float*)d_in[8];
    const float* w_proj = (const float*)d_in[9];
    const float* b_proj = (const float*)d_in[10];
    const float* w_tb1  = (const float*)d_in[11];
    const float* b_tb1  = (const float*)d_in[12];
    const float* w_tb2  = (const float*)d_in[13];
    const float* b_tb2  = (const float*)d_in[14];
    float* out = (float*)d_out;

    __half *xh, *Oh, *Wq, *Wk, *Wv, *Wp, *Qh, *Kh, *Vh;
    cudaGetSymbolAddress((void**)&xh, g_xh);
    cudaGetSymbolAddress((void**)&Oh, g_Oh);
    cudaGetSymbolAddress((void**)&Wq, g_Wq);
    cudaGetSymbolAddress((void**)&Wk, g_Wk);
    cudaGetSymbolAddress((void**)&Wv, g_Wv);
    cudaGetSymbolAddress((void**)&Wp, g_Wp);
    cudaGetSymbolAddress((void**)&Qh, g_Qh);
    cudaGetSymbolAddress((void**)&Kh, g_Kh);
    cudaGetSymbolAddress((void**)&Vh, g_Vh);

    // 1) temporal bias
    bias_kernel<<<(BATCH*SEQ*SEQ + 255) / 256, 256>>>(mat, w_tb1, b_tb1, w_tb2, b_tb2);

    // 2) converts
    f32tof16<<<(MROWS*DMODEL/4 + 255)/256, 256>>>(x, xh, MROWS*DMODEL/4);
    wtrans<<<dim3(32, 32, 4), dim3(32, 8)>>>(wq, wk, wv, w_proj);

    // 3) QKV projections (HMMA, fp16 out)
    gemm_tc<__half><<<dim3(DMODEL/128, MROWS/128, 3), 256>>>(
        xh, Wq, Wk, Wv, bq, bk, bv, Qh, Kh, Vh);

    // 4) HMMA flash attention (fp16 out)
    attn_hmma<<<dim3(SEQ/64, NHEAD, BATCH), 128>>>(pm);

    // 5) output projection (HMMA, fp32 out)
    gemm_tc<float><<<dim3(DMODEL/128, MROWS/128, 1), 256>>>(
        Oh, Wp, Wp, Wp, b_proj, b_proj, b_proj, out, out, out);
}

// round 5
// speedup vs baseline: 6.4389x; 1.1090x over previous
#include <cuda_runtime.h>
#include <cuda_fp16.h>
#include <math.h>
#include <stdint.h>

// Problem constants
#define BATCH 8
#define SEQ   512
#define DMODEL 1024
#define NHEAD 16
#define DK    64
#define TBDIM 64
#define SCALE 0.125f
#define NEGINF -1e30f
#define MROWS (BATCH*SEQ)          // 4096

// ---------------------------------------------------------------------------
// Scratch (device globals)
// ---------------------------------------------------------------------------
__device__ float  g_Tb[BATCH*SEQ*SEQ];      // temporal bias (B,S,S) fp32
__device__ __half g_xh[MROWS*DMODEL];       // x in fp16
__device__ __half g_Qh[MROWS*DMODEL];       // Q (B,S,D) fp16, head h at col h*64
__device__ __half g_Kh[MROWS*DMODEL];
__device__ __half g_Vh[MROWS*DMODEL];
__device__ __half g_Oh[MROWS*DMODEL];       // attention output fp16
__device__ __half g_Wq[DMODEL*DMODEL];      // W^T fp16: [N][K]
__device__ __half g_Wk[DMODEL*DMODEL];
__device__ __half g_Wv[DMODEL*DMODEL];
__device__ __half g_Wp[DMODEL*DMODEL];

// ---------------------------------------------------------------------------
// PTX helpers
// ---------------------------------------------------------------------------
__device__ __forceinline__ uint32_t smem_u32(const void* p) {
    uint32_t a;
    asm("{ .reg .u64 t; cvta.to.shared.u64 t, %1; cvt.u32.u64 %0, t; }" : "=r"(a) : "l"(p));
    return a;
}
__device__ __forceinline__ void ldsm_x4(uint32_t (&r)[4], uint32_t addr) {
    asm volatile("ldmatrix.sync.aligned.m8n8.x4.shared.b16 {%0,%1,%2,%3}, [%4];"
        : "=r"(r[0]), "=r"(r[1]), "=r"(r[2]), "=r"(r[3]) : "r"(addr));
}
__device__ __forceinline__ void ldsm_x4t(uint32_t (&r)[4], uint32_t addr) {
    asm volatile("ldmatrix.sync.aligned.m8n8.x4.trans.shared.b16 {%0,%1,%2,%3}, [%4];"
        : "=r"(r[0]), "=r"(r[1]), "=r"(r[2]), "=r"(r[3]) : "r"(addr));
}
__device__ __forceinline__ void mma16816(float (&d)[4], const uint32_t (&a)[4],
                                         const uint32_t* b) {
    asm volatile("mma.sync.aligned.m16n8k16.row.col.f32.f16.f16.f32 "
        "{%0,%1,%2,%3}, {%4,%5,%6,%7}, {%8,%9}, {%0,%1,%2,%3};"
        : "+f"(d[0]), "+f"(d[1]), "+f"(d[2]), "+f"(d[3])
        : "r"(a[0]), "r"(a[1]), "r"(a[2]), "r"(a[3]), "r"(b[0]), "r"(b[1]));
}
__device__ __forceinline__ uint32_t packh2(float a, float b) {
    __half2 h = __floats2half2_rn(a, b);
    return *(uint32_t*)&h;
}
#define CP_ASYNC16(dst, src) \
    asm volatile("cp.async.cg.shared.global [%0], [%1], 16;" :: "r"(dst), "l"(src) : "memory")
#define CP_COMMIT() asm volatile("cp.async.commit_group;" ::: "memory")
#define CP_WAIT(n)  asm volatile("cp.async.wait_group %0;" :: "n"(n) : "memory")

// ---------------------------------------------------------------------------
// Kernel 1: temporal bias precompute (x4 vectorized: 4 independent FMA chains)
// ---------------------------------------------------------------------------
__global__ void bias_kernel(const float* __restrict__ mat,
                            const float* __restrict__ w1,
                            const float* __restrict__ b1,
                            const float* __restrict__ w2,
                            const float* __restrict__ b2) {
    __shared__ float sw1[TBDIM], sb1[TBDIM], sw2[TBDIM];
    int tid = threadIdx.x;
    if (tid < TBDIM) { sw1[tid] = w1[tid]; sb1[tid] = b1[tid]; sw2[tid] = w2[tid]; }
    __syncthreads();
    int i4 = blockIdx.x * blockDim.x + tid;
    if (i4 >= BATCH*SEQ*SEQ/4) return;
    float4 mv = ((const float4*)mat)[i4];
    const float E = 2.718281828459045f;
    float t0 = 1.0f / logf(E + mv.x);
    float t1 = 1.0f / logf(E + mv.y);
    float t2 = 1.0f / logf(E + mv.z);
    float t3 = 1.0f / logf(E + mv.w);
    float a0 = b2[0], a1 = a0, a2 = a0, a3 = a0;
#pragma unroll
    for (int j = 0; j < TBDIM; j++) {
        float w = sw1[j], bb = sb1[j], v = sw2[j];
        float h0 = fmaf(t0, w, bb); h0 = (h0 >= 0.0f) ? h0 : 0.2f * h0;
        float h1 = fmaf(t1, w, bb); h1 = (h1 >= 0.0f) ? h1 : 0.2f * h1;
        float h2 = fmaf(t2, w, bb); h2 = (h2 >= 0.0f) ? h2 : 0.2f * h2;
        float h3 = fmaf(t3, w, bb); h3 = (h3 >= 0.0f) ? h3 : 0.2f * h3;
        a0 = fmaf(h0, v, a0); a1 = fmaf(h1, v, a1);
        a2 = fmaf(h2, v, a2); a3 = fmaf(h3, v, a3);
    }
    float4 r = {a0, a1, a2, a3};
    ((float4*)g_Tb)[i4] = r;
}

// ---------------------------------------------------------------------------
// Kernel 2a: fp32 -> fp16 convert
// ---------------------------------------------------------------------------
__global__ void f32tof16(const float* __restrict__ s, __half* __restrict__ d, int n4) {
    int i = blockIdx.x * blockDim.x + threadIdx.x;
    if (i >= n4) return;
    float4 v = ((const float4*)s)[i];
    ((__half2*)d)[2*i]   = __floats2half2_rn(v.x, v.y);
    ((__half2*)d)[2*i+1] = __floats2half2_rn(v.z, v.w);
}

// ---------------------------------------------------------------------------
// Kernel 2b: weight transpose-convert.  Wt[n][k] = (half)W[k][n]
// ---------------------------------------------------------------------------
__global__ void wtrans(const float* __restrict__ w0, const float* __restrict__ w1,
                       const float* __restrict__ w2, const float* __restrict__ w3) {
    int z = blockIdx.z;
    const float* W = (z==0) ? w0 : (z==1) ? w1 : (z==2) ? w2 : w3;
    __half* O      = (z==0) ? g_Wq : (z==1) ? g_Wk : (z==2) ? g_Wv : g_Wp;
    __shared__ float t[32][33];
    int kx = blockIdx.x * 32, ny = blockIdx.y * 32;
    int tx = threadIdx.x, ty = threadIdx.y;
#pragma unroll
    for (int i = 0; i < 4; i++)
        t[ty + i*8][tx] = W[(size_t)(kx + ty + i*8) * DMODEL + ny + tx];
    __syncthreads();
#pragma unroll
    for (int i = 0; i < 4; i++)
        O[(size_t)(ny + ty + i*8) * DMODEL + kx + tx] = __float2half(t[tx][ty + i*8]);
}

// ---------------------------------------------------------------------------
// Kernel 3: HMMA GEMM, BK=64, dynamic smem 64KB, double-buffered cp.async.
// CTA 128x128, 256 threads (8 warps at 64x32). Rows are 128B, swizzle c^(row&7).
// ---------------------------------------------------------------------------
#define ROWB 128
#define TILEB (128*ROWB)   // 16 KB per operand tile
#define GEMM_SMEM (4*TILEB)

__device__ __forceinline__ void store2(float* C, size_t idx, float a, float b) {
    float2 v = {a, b}; *(float2*)&C[idx] = v;
}
__device__ __forceinline__ void store2(__half* C, size_t idx, float a, float b) {
    *(__half2*)&C[idx] = __floats2half2_rn(a, b);
}

template <typename TOUT>
__global__ void __launch_bounds__(256, 2) gemm_tc(
    const __half* __restrict__ A,
    const __half* __restrict__ B0, const __half* __restrict__ B1, const __half* __restrict__ B2,
    const float* __restrict__ bi0, const float* __restrict__ bi1, const float* __restrict__ bi2,
    TOUT* __restrict__ C0, TOUT* __restrict__ C1, TOUT* __restrict__ C2)
{
    int z = blockIdx.z;
    const __half* Bt   = (z==0) ? B0  : (z==1) ? B1  : B2;
    const float*  bias = (z==0) ? bi0 : (z==1) ? bi1 : bi2;
    TOUT*         C    = (z==0) ? C0  : (z==1) ? C1  : C2;

    extern __shared__ __align__(128) unsigned char sm[];   // [buf][A|B] 4 x 16KB

    int tid  = threadIdx.x;
    int lane = tid & 31;
    int wid  = tid >> 5;
    int wm   = (wid & 1) * 64;
    int wn   = (wid >> 1) * 32;
    int m0 = blockIdx.y * 128, n0 = blockIdx.x * 128;

    uint32_t sbase = smem_u32(sm);

    // loads: 128 rows x 8 chunks = 1024 chunks per operand; 4 per thread
    uint32_t swo[4];
    const __half *gA[4], *gB[4];
#pragma unroll
    for (int i = 0; i < 4; i++) {
        int id = tid + i * 256;
        int r = id >> 3, c = id & 7;
        swo[i] = r * ROWB + ((c ^ (r & 7)) * 16);
        gA[i] = A  + (size_t)(m0 + r) * DMODEL + c * 8;
        gB[i] = Bt + (size_t)(n0 + r) * DMODEL + c * 8;
    }

    float acc[4][4][4] = {};

    // prefetch tile 0
#pragma unroll
    for (int i = 0; i < 4; i++) {
        CP_ASYNC16(sbase + swo[i],         gA[i]);
        CP_ASYNC16(sbase + TILEB + swo[i], gB[i]);
    }
    CP_COMMIT();

    const int NKT = DMODEL / 64;   // 16
    for (int kt = 0; kt < NKT; kt++) {
        int cur = kt & 1;
        if (kt + 1 < NKT) {
            uint32_t ab = sbase + ((kt + 1) & 1) * 2 * TILEB;
            int koff = (kt + 1) * 64;
#pragma unroll
            for (int i = 0; i < 4; i++) {
                CP_ASYNC16(ab + swo[i],         gA[i] + koff);
                CP_ASYNC16(ab + TILEB + swo[i], gB[i] + koff);
            }
            CP_COMMIT();
            CP_WAIT(1);
        } else {
            CP_WAIT(0);
        }
        __syncthreads();

        uint32_t aBase = sbase + cur * 2 * TILEB;
        uint32_t bBase = aBase + TILEB;

#pragma unroll
        for (int ks = 0; ks < 4; ks++) {
            uint32_t af[4][4];
#pragma unroll
            for (int mf = 0; mf < 4; mf++) {
                int row = wm + mf * 16 + (lane & 15);
                int ch  = 2 * ks + (lane >> 4);
                ldsm_x4(af[mf], aBase + row * ROWB + ((ch ^ (row & 7)) * 16));
            }
            uint32_t bf[2][4];   // [pair][4 regs] -> nf = pair*2 + (reghalf)
#pragma unroll
            for (int p = 0; p < 2; p++) {
                int row = wn + p * 16 + (lane & 7) + ((lane >> 4) << 3);
                int ch  = 2 * ks + ((lane >> 3) & 1);
                ldsm_x4(bf[p], bBase + row * ROWB + ((ch ^ (row & 7)) * 16));
            }
#pragma unroll
            for (int mf = 0; mf < 4; mf++) {
                mma16816(acc[mf][0], af[mf], &bf[0][0]);
                mma16816(acc[mf][1], af[mf], &bf[0][2]);
                mma16816(acc[mf][2], af[mf], &bf[1][0]);
                mma16816(acc[mf][3], af[mf], &bf[1][2]);
            }
        }
        __syncthreads();
    }

    int g = lane >> 2, t = lane & 3;
#pragma unroll
    for (int mf = 0; mf < 4; mf++) {
        int r0 = m0 + wm + mf * 16 + g;
#pragma unroll
        for (int nf = 0; nf < 4; nf++) {
            int c = n0 + wn + nf * 8 + t * 2;
            float bx = __ldg(&bias[c]), by = __ldg(&bias[c + 1]);
            store2(C, (size_t)r0 * DMODEL + c,       acc[mf][nf][0] + bx, acc[mf][nf][1] + by);
            store2(C, (size_t)(r0 + 8) * DMODEL + c, acc[mf][nf][2] + bx, acc[mf][nf][3] + by);
        }
    }
}

// ---------------------------------------------------------------------------
// Kernel 4: HMMA causal flash attention (x4 ldsm everywhere).
// 128 threads (4 warps), block = (q-tile 64, head, batch).
// Smem rows: 64 halves = 128B = 8 chunks; swizzle ch ^= row&7.
// ---------------------------------------------------------------------------
__global__ void __launch_bounds__(128) attn_hmma(const int* __restrict__ pm) {
    __shared__ __align__(128) __half Qs[64*64];
    __shared__ __align__(128) __half Ks[2][64*64];
    __shared__ __align__(128) __half Vs[2][64*64];
    __shared__ int spm[2][64];

    int qt = blockIdx.x, h = blockIdx.y, b = blockIdx.z;
    int tid = threadIdx.x, lane = tid & 31, wid = tid >> 5;
    int wrow = wid * 16;
    int q0 = qt * 64;
    int g = lane >> 2, t = lane & 3;

    const __half* Qg = g_Qh + (size_t)b * SEQ * DMODEL + h * DK;
    const __half* Kg = g_Kh + (size_t)b * SEQ * DMODEL + h * DK;
    const __half* Vg = g_Vh + (size_t)b * SEQ * DMODEL + h * DK;
    const float* Tbb = g_Tb + (size_t)b * SEQ * SEQ;

    uint32_t qb  = smem_u32(Qs);
    uint32_t kb_[2] = { smem_u32(Ks[0]), smem_u32(Ks[1]) };
    uint32_t vb_[2] = { smem_u32(Vs[0]), smem_u32(Vs[1]) };

#pragma unroll
    for (int i = 0; i < 4; i++) {
        int id = tid + i * 128;
        int rr = id >> 3, c = id & 7;
        uint32_t sw = rr * 128 + ((c ^ (rr & 7)) * 16);
        CP_ASYNC16(qb + sw, Qg + (size_t)(q0 + rr) * DMODEL + c * 8);
        CP_ASYNC16(kb_[0] + sw, Kg + (size_t)rr * DMODEL + c * 8);
        CP_ASYNC16(vb_[0] + sw, Vg + (size_t)rr * DMODEL + c * 8);
    }
    if (tid < 16)
        CP_ASYNC16(smem_u32(spm[0]) + tid * 16, pm + b * SEQ + tid * 4);
    CP_COMMIT();

    float m0 = NEGINF, m1 = NEGINF, l0 = 0.0f, l1 = 0.0f;
    float o[8][4] = {};
    int qgl0 = q0 + wrow + g;
    int qgl1 = qgl0 + 8;

    for (int kt = 0; kt <= qt; kt++) {
        int cur = kt & 1;
        if (kt < qt) {
            int nxt = (kt + 1) & 1;
#pragma unroll
            for (int i = 0; i < 4; i++) {
                int id = tid + i * 128;
                int rr = id >> 3, c = id & 7;
                uint32_t sw = rr * 128 + ((c ^ (rr & 7)) * 16);
                CP_ASYNC16(kb_[nxt] + sw, Kg + (size_t)((kt+1)*64 + rr) * DMODEL + c * 8);
                CP_ASYNC16(vb_[nxt] + sw, Vg + (size_t)((kt+1)*64 + rr) * DMODEL + c * 8);
            }
            if (tid < 16)
                CP_ASYNC16(smem_u32(spm[nxt]) + tid * 16, pm + b * SEQ + (kt+1)*64 + tid * 4);
            CP_COMMIT();
            CP_WAIT(1);
        } else {
            CP_WAIT(0);
        }
        __syncthreads();

        uint32_t kb = kb_[cur], vb = vb_[cur];
        const int* pmc = spm[cur];

        // ---- S = Q K^T ----
        float s[8][4] = {};
#pragma unroll
        for (int ks = 0; ks < 4; ks++) {
            uint32_t a[4];
            {
                int row = wrow + (lane & 15);
                int ch  = ks * 2 + (lane >> 4);
                ldsm_x4(a, qb + row * 128 + ((ch ^ (row & 7)) * 16));
            }
#pragma unroll
            for (int p = 0; p < 4; p++) {
                uint32_t bfr[4];
                int row = p * 16 + (lane & 7) + ((lane >> 4) << 3);
                int ch  = ks * 2 + ((lane >> 3) & 1);
                ldsm_x4(bfr, kb + row * 128 + ((ch ^ (row & 7)) * 16));
                mma16816(s[2*p],   a, &bfr[0]);
                mma16816(s[2*p+1], a, &bfr[2]);
            }
        }

        // ---- scale + bias + masks + row max ----
        float mx0 = m0, mx1 = m1;
#pragma unroll
        for (int nf = 0; nf < 8; nf++) {
            int coll = nf * 8 + t * 2;
            int kg = kt * 64 + coll;
            float2 tb0 = *(const float2*)&Tbb[(size_t)qgl0 * SEQ + kg];
            float2 tb1 = *(const float2*)&Tbb[(size_t)qgl1 * SEQ + kg];
            float v00 = fmaf(s[nf][0], SCALE, tb0.x);
            float v01 = fmaf(s[nf][1], SCALE, tb0.y);
            float v10 = fmaf(s[nf][2], SCALE, tb1.x);
            float v11 = fmaf(s[nf][3], SCALE, tb1.y);
            bool z0 = (pmc[coll] == 0), z1 = (pmc[coll + 1] == 0);
            if (z0 || kg     > qgl0) v00 = NEGINF;
            if (z1 || kg + 1 > qgl0) v01 = NEGINF;
            if (z0 || kg     > qgl1) v10 = NEGINF;
            if (z1 || kg + 1 > qgl1) v11 = NEGINF;
            s[nf][0] = v00; s[nf][1] = v01; s[nf][2] = v10; s[nf][3] = v11;
            mx0 = fmaxf(mx0, fmaxf(v00, v01));
            mx1 = fmaxf(mx1, fmaxf(v10, v11));
        }
        mx0 = fmaxf(mx0, __shfl_xor_sync(0xffffffffu, mx0, 1));
        mx0 = fmaxf(mx0, __shfl_xor_sync(0xffffffffu, mx0, 2));
        mx1 = fmaxf(mx1, __shfl_xor_sync(0xffffffffu, mx1, 1));
        mx1 = fmaxf(mx1, __shfl_xor_sync(0xffffffffu, mx1, 2));

        float corr0 = __expf(m0 - mx0);
        float corr1 = __expf(m1 - mx1);
        m0 = mx0; m1 = mx1;

        float sum0 = 0.0f, sum1 = 0.0f;
#pragma unroll
        for (int nf = 0; nf < 8; nf++) {
            float p00 = __expf(s[nf][0] - mx0);
            float p01 = __expf(s[nf][1] - mx0);
            float p10 = __expf(s[nf][2] - mx1);
            float p11 = __expf(s[nf][3] - mx1);
            s[nf][0] = p00; s[nf][1] = p01; s[nf][2] = p10; s[nf][3] = p11;
            sum0 += p00 + p01;
            sum1 += p10 + p11;
        }
        sum0 += __shfl_xor_sync(0xffffffffu, sum0, 1);
        sum0 += __shfl_xor_sync(0xffffffffu, sum0, 2);
        sum1 += __shfl_xor_sync(0xffffffffu, sum1, 1);
        sum1 += __shfl_xor_sync(0xffffffffu, sum1, 2);
        l0 = l0 * corr0 + sum0;
        l1 = l1 * corr1 + sum1;

#pragma unroll
        for (int nf = 0; nf < 8; nf++) {
            o[nf][0] *= corr0; o[nf][1] *= corr0;
            o[nf][2] *= corr1; o[nf][3] *= corr1;
        }
        uint32_t pa[4][4];
#pragma unroll
        for (int kk = 0; kk < 4; kk++) {
            pa[kk][0] = packh2(s[2*kk][0],   s[2*kk][1]);
            pa[kk][1] = packh2(s[2*kk][2],   s[2*kk][3]);
            pa[kk][2] = packh2(s[2*kk+1][0], s[2*kk+1][1]);
            pa[kk][3] = packh2(s[2*kk+1][2], s[2*kk+1][3]);
        }

        // ---- O += P V  (x4 trans: two d-chunks per ldsm) ----
#pragma unroll
        for (int kk = 0; kk < 4; kk++) {
#pragma unroll
            for (int p = 0; p < 4; p++) {
                uint32_t bfr[4];
                int row = kk * 16 + (lane & 7) + (((lane >> 3) & 1) << 3);
                int ch  = p * 2 + ((lane >> 4) & 1);
                ldsm_x4t(bfr, vb + row * 128 + ((ch ^ (row & 7)) * 16));
                mma16816(o[2*p],   pa[kk], &bfr[0]);
                mma16816(o[2*p+1], pa[kk], &bfr[2]);
            }
        }
        __syncthreads();
    }

    float inv0 = 1.0f / l0, inv1 = 1.0f / l1;
    __half* Og = g_Oh + (size_t)b * SEQ * DMODEL + h * DK;
#pragma unroll
    for (int nf = 0; nf < 8; nf++) {
        int coll = nf * 8 + t * 2;
        *(__half2*)&Og[(size_t)(q0 + wrow + g) * DMODEL + coll] =
            __floats2half2_rn(o[nf][0] * inv0, o[nf][1] * inv0);
        *(__half2*)&Og[(size_t)(q0 + wrow + g + 8) * DMODEL + coll] =
            __floats2half2_rn(o[nf][2] * inv1, o[nf][3] * inv1);
    }
}

// ---------------------------------------------------------------------------
extern "C" void kernel_launch(void* const* d_in, const int* in_sizes, int n_in,
                              void* d_out, int out_size) {
    const float* x      = (const float*)d_in[0];
    const int*   pm     = (const int*)  d_in[1];
    const float* mat    = (const float*)d_in[2];
    const float* wq     = (const float*)d_in[3];
    const float* bq     = (const float*)d_in[4];
    const float* wk     = (const float*)d_in[5];
    const float* bk     = (const float*)d_in[6];
    const float* wv     = (const float*)d_in[7];
    const float* bv     = (const float*)d_in[8];
    const float* w_proj = (const float*)d_in[9];
    const float* b_proj = (const float*)d_in[10];
    const float* w_tb1  = (const float*)d_in[11];
    const float* b_tb1  = (const float*)d_in[12];
    const float* w_tb2  = (const float*)d_in[13];
    const float* b_tb2  = (const float*)d_in[14];
    float* out = (float*)d_out;

    __half *xh, *Oh, *Wq, *Wk, *Wv, *Wp, *Qh, *Kh, *Vh;
    cudaGetSymbolAddress((void**)&xh, g_xh);
    cudaGetSymbolAddress((void**)&Oh, g_Oh);
    cudaGetSymbolAddress((void**)&Wq, g_Wq);
    cudaGetSymbolAddress((void**)&Wk, g_Wk);
    cudaGetSymbolAddress((void**)&Wv, g_Wv);
    cudaGetSymbolAddress((void**)&Wp, g_Wp);
    cudaGetSymbolAddress((void**)&Qh, g_Qh);
    cudaGetSymbolAddress((void**)&Kh, g_Kh);
    cudaGetSymbolAddress((void**)&Vh, g_Vh);

    cudaFuncSetAttribute(gemm_tc<__half>, cudaFuncAttributeMaxDynamicSharedMemorySize, GEMM_SMEM);
    cudaFuncSetAttribute(gemm_tc<float>,  cudaFuncAttributeMaxDynamicSharedMemorySize, GEMM_SMEM);

    // 1) temporal bias
    bias_kernel<<<(BATCH*SEQ*SEQ/4 + 255) / 256, 256>>>(mat, w_tb1, b_tb1, w_tb2, b_tb2);

    // 2) converts
    f32tof16<<<(MROWS*DMODEL/4 + 255)/256, 256>>>(x, xh, MROWS*DMODEL/4);
    wtrans<<<dim3(32, 32, 4), dim3(32, 8)>>>(wq, wk, wv, w_proj);

    // 3) QKV projections (HMMA, fp16 out)
    gemm_tc<__half><<<dim3(DMODEL/128, MROWS/128, 3), 256, GEMM_SMEM>>>(
        xh, Wq, Wk, Wv, bq, bk, bv, Qh, Kh, Vh);

    // 4) HMMA flash attention (fp16 out)
    attn_hmma<<<dim3(SEQ/64, NHEAD, BATCH), 128>>>(pm);

    // 5) output projection (HMMA, fp32 out)
    gemm_tc<float><<<dim3(DMODEL/128, MROWS/128, 1), 256, GEMM_SMEM>>>(
        Oh, Wp, Wp, Wp, b_proj, b_proj, b_proj, out, out, out);
}